// round 1
// baseline (speedup 1.0000x reference)
#include <cuda_runtime.h>

// AffineToDenseShift: out[b,d,h,w,i] = (A[b] @ mesh + t[b] - mesh)[i]
//   with mesh_j = coord_j - center_j (SHIFT_CENTER=True).
// Folded form: out_i = K_i + cd_i*d + ch_i*h + cw_i*w
//   cd_i = A[b,i,0]-d(i==0), ch_i = A[b,i,1]-d(i==1), cw_i = A[b,i,2]-d(i==2)
//   K_i  = t[b,i] - cd_i*79.5 - ch_i*95.5 - cw_i*111.5
//
// Store-bound kernel: 330 MB of fp32 output, ~192 B input.

#define BB 4
#define DD 160
#define HH 192
#define WW 224
// total voxels = 4*160*192*224 = 27,525,120 (divisible by 4)
#define TOTAL_VOX (BB * DD * HH * WW)
#define VOX_PER_THREAD 4
#define THREADS 256

// Scratch for folded coefficients: [b][i] -> {K, cd, ch, cw}
__device__ float4 g_coef[BB * 3];

__global__ void prep_kernel(const float* __restrict__ m) {
    int t = threadIdx.x;
    if (t >= BB * 3) return;
    int b = t / 3;
    int i = t - 3 * b;
    const float* row = m + b * 12 + i * 4;  // matrix[b, i, :]
    float cd = row[0] - (i == 0 ? 1.0f : 0.0f);
    float ch = row[1] - (i == 1 ? 1.0f : 0.0f);
    float cw = row[2] - (i == 2 ? 1.0f : 0.0f);
    float K  = row[3] - cd * ((float)(DD - 1) * 0.5f)
                      - ch * ((float)(HH - 1) * 0.5f)
                      - cw * ((float)(WW - 1) * 0.5f);
    g_coef[t] = make_float4(K, cd, ch, cw);
}

__global__ void __launch_bounds__(THREADS)
affine_shift_kernel(float* __restrict__ out) {
    unsigned v = VOX_PER_THREAD * (blockIdx.x * THREADS + threadIdx.x);
    if (v >= (unsigned)TOTAL_VOX) return;

    // Decode (b, d, h, w). Since W % 4 == 0 and v % 4 == 0, the 4 voxels
    // v..v+3 share the same (b, d, h) and have w, w+1, w+2, w+3.
    unsigned w    = v % WW;
    unsigned rest = v / WW;
    unsigned h    = rest % HH;
    unsigned bd   = rest / HH;
    unsigned b    = bd / DD;
    unsigned d    = bd - b * DD;

    float4 c0 = g_coef[b * 3 + 0];
    float4 c1 = g_coef[b * 3 + 1];
    float4 c2 = g_coef[b * 3 + 2];

    float fd = (float)d, fh = (float)h, fw = (float)w;

    // Base value at voxel (d, h, w) for each of the 3 components.
    float b0 = fmaf(c0.w, fw, fmaf(c0.z, fh, fmaf(c0.y, fd, c0.x)));
    float b1 = fmaf(c1.w, fw, fmaf(c1.z, fh, fmaf(c1.y, fd, c1.x)));
    float b2 = fmaf(c2.w, fw, fmaf(c2.z, fh, fmaf(c2.y, fd, c2.x)));

    // 4 voxels * 3 comps = 12 floats = 3x float4, 16B-aligned (v*3 % 4 == 0).
    float4* dst = (float4*)(out + (size_t)v * 3);

    float4 o0 = make_float4(b0,
                            b1,
                            b2,
                            b0 + c0.w);
    float4 o1 = make_float4(b1 + c1.w,
                            b2 + c2.w,
                            fmaf(2.0f, c0.w, b0),
                            fmaf(2.0f, c1.w, b1));
    float4 o2 = make_float4(fmaf(2.0f, c2.w, b2),
                            fmaf(3.0f, c0.w, b0),
                            fmaf(3.0f, c1.w, b1),
                            fmaf(3.0f, c2.w, b2));

    // Streaming stores: 330 MB output, zero reuse -> don't pollute L2.
    __stcs(dst + 0, o0);
    __stcs(dst + 1, o1);
    __stcs(dst + 2, o2);
}

extern "C" void kernel_launch(void* const* d_in, const int* in_sizes, int n_in,
                              void* d_out, int out_size) {
    (void)in_sizes; (void)n_in; (void)out_size;
    const float* matrix = (const float*)d_in[0];
    float* out = (float*)d_out;

    prep_kernel<<<1, 32>>>(matrix);

    const unsigned n_threads = TOTAL_VOX / VOX_PER_THREAD;      // 6,881,280
    const unsigned n_blocks  = (n_threads + THREADS - 1) / THREADS;  // 26,880
    affine_shift_kernel<<<n_blocks, THREADS>>>(out);
}

// round 3
// speedup vs baseline: 1.7452x; 1.7452x over previous
#include <cuda_runtime.h>
#include <cstdint>

// AffineToDenseShift: out[b,d,h,w,i] = K_i + cd_i*d + ch_i*h + cw_i*w
// (coefficients folded from A, t, and the centered mesh).
//
// R1 ncu: DRAM 38%, L2 66%, L1 80.6% -> per-thread STG path (L1tex) is the
// bottleneck, not HBM. R2/R3: stage each CTA's 48KB output tile in SMEM and
// drain it with one TMA bulk store (cp.async.bulk), bypassing L1tex.

#define BB 4
#define DD 160
#define HH 192
#define WW 224
#define TOTAL_VOX (BB * DD * HH * WW)        // 27,525,120

#define THREADS 256
#define ITERS 4
#define VOX_PER_ITER (THREADS * 4)           // 1024 voxels per iteration
#define CTA_VOX (VOX_PER_ITER * ITERS)       // 4096 voxels per CTA
#define CTA_FLOATS (CTA_VOX * 3)             // 12288 floats
#define CTA_BYTES (CTA_FLOATS * 4)           // 49152 B = 48 KB
#define GRID (TOTAL_VOX / CTA_VOX)           // 6720 CTAs (exact)

// Folded coefficients: [b][i] -> {K, cd, ch, cw}
__device__ float4 g_coef[BB * 3];

__global__ void prep_kernel(const float* __restrict__ m) {
    int t = threadIdx.x;
    if (t >= BB * 3) return;
    int b = t / 3;
    int i = t - 3 * b;
    const float* row = m + b * 12 + i * 4;   // matrix[b, i, :]
    float cd = row[0] - (i == 0 ? 1.0f : 0.0f);
    float ch = row[1] - (i == 1 ? 1.0f : 0.0f);
    float cw = row[2] - (i == 2 ? 1.0f : 0.0f);
    float K  = row[3] - cd * ((float)(DD - 1) * 0.5f)
                      - ch * ((float)(HH - 1) * 0.5f)
                      - cw * ((float)(WW - 1) * 0.5f);
    g_coef[t] = make_float4(K, cd, ch, cw);
}

__global__ void __launch_bounds__(THREADS)
affine_shift_tma_kernel(float* __restrict__ out) {
    __shared__ __align__(128) float smem[CTA_FLOATS];

    const unsigned cta_base = blockIdx.x * CTA_VOX;

    // Each CTA lies entirely inside one batch (batch = 4096*1680 voxels).
    const unsigned b = cta_base / (DD * HH * WW);
    const float4 c0 = g_coef[b * 3 + 0];
    const float4 c1 = g_coef[b * 3 + 1];
    const float4 c2 = g_coef[b * 3 + 2];

#pragma unroll
    for (int j = 0; j < ITERS; j++) {
        const unsigned local_v = j * VOX_PER_ITER + threadIdx.x * 4;
        const unsigned v = cta_base + local_v;

        // v % 4 == 0 and WW % 4 == 0: the 4 voxels share (d,h), w..w+3.
        unsigned w    = v % WW;
        unsigned rest = v / WW;
        unsigned h    = rest % HH;
        unsigned d    = (rest / HH) % DD;

        float fd = (float)d, fh = (float)h, fw = (float)w;

        float b0 = fmaf(c0.w, fw, fmaf(c0.z, fh, fmaf(c0.y, fd, c0.x)));
        float b1 = fmaf(c1.w, fw, fmaf(c1.z, fh, fmaf(c1.y, fd, c1.x)));
        float b2 = fmaf(c2.w, fw, fmaf(c2.z, fh, fmaf(c2.y, fd, c2.x)));

        float4 o0 = make_float4(b0, b1, b2, b0 + c0.w);
        float4 o1 = make_float4(b1 + c1.w,
                                b2 + c2.w,
                                fmaf(2.0f, c0.w, b0),
                                fmaf(2.0f, c1.w, b1));
        float4 o2 = make_float4(fmaf(2.0f, c2.w, b2),
                                fmaf(3.0f, c0.w, b0),
                                fmaf(3.0f, c1.w, b1),
                                fmaf(3.0f, c2.w, b2));

        // SMEM mirrors the global layout exactly (offset = local float idx).
        // Lane stride 48 B for STS.128 is bank-conflict-free.
        float4* s = (float4*)(smem + (size_t)local_v * 3);
        s[0] = o0;
        s[1] = o1;
        s[2] = o2;
    }

    __syncthreads();

    if (threadIdx.x == 0) {
        // Order the generic-proxy STS writes before the async-proxy TMA read.
        asm volatile("fence.proxy.async.shared::cta;" ::: "memory");
        uint32_t saddr = (uint32_t)__cvta_generic_to_shared(smem);
        float* gdst = out + (size_t)cta_base * 3;
        uint32_t nbytes = CTA_BYTES;
        asm volatile(
            "cp.async.bulk.global.shared::cta.bulk_group [%0], [%1], %2;"
            :: "l"(gdst), "r"(saddr), "r"(nbytes)
            : "memory");
        asm volatile("cp.async.bulk.commit_group;" ::: "memory");
        // Wait until the bulk store has finished READING smem before any
        // thread of the CTA may exit.
        asm volatile("cp.async.bulk.wait_group.read 0;" ::: "memory");
    }
    __syncthreads();
}

extern "C" void kernel_launch(void* const* d_in, const int* in_sizes, int n_in,
                              void* d_out, int out_size) {
    (void)in_sizes; (void)n_in; (void)out_size;
    const float* matrix = (const float*)d_in[0];
    float* out = (float*)d_out;

    prep_kernel<<<1, 32>>>(matrix);
    affine_shift_tma_kernel<<<GRID, THREADS>>>(out);
}

// round 4
// speedup vs baseline: 1.7862x; 1.0235x over previous
#include <cuda_runtime.h>
#include <cstdint>

// AffineToDenseShift: out[b,d,h,w,i] = K_i + cd_i*d + ch_i*h + cw_i*w
// (coefficients folded from A, t, and the centered mesh).
//
// R3: TMA bulk store (48KB tile) -> 51.6us, DRAM 69.6% (bursty drains,
// occ 46.5%). R4: 24KB tiles (8 CTAs/SM, 100% occ), per-chunk TMA issue
// to overlap drain with compute, and prep folded into the main kernel
// (single launch).

#define BB 4
#define DD 160
#define HH 192
#define WW 224
#define TOTAL_VOX (BB * DD * HH * WW)        // 27,525,120

#define THREADS 256
#define ITERS 2
#define VOX_PER_ITER (THREADS * 4)           // 1024 voxels per chunk
#define CTA_VOX (VOX_PER_ITER * ITERS)       // 2048 voxels per CTA
#define CHUNK_FLOATS (VOX_PER_ITER * 3)      // 3072 floats
#define CHUNK_BYTES (CHUNK_FLOATS * 4)       // 12288 B
#define CTA_FLOATS (CTA_VOX * 3)             // 6144 floats = 24 KB
#define GRID (TOTAL_VOX / CTA_VOX)           // 13440 CTAs (exact; 3360/batch)

__global__ void __launch_bounds__(THREADS)
affine_shift_kernel(const float* __restrict__ m, float* __restrict__ out) {
    __shared__ __align__(128) float smem[CTA_FLOATS];

    const unsigned cta_base = blockIdx.x * CTA_VOX;
    const unsigned b = cta_base / (DD * HH * WW);  // CTA never crosses a batch

    // Fold coefficients from matrix[b] (12 floats, L1-broadcast).
    const float* mb = m + b * 12;
    const float cdx = DD - 1, chx = HH - 1, cwx = WW - 1;

    float cd0 = __ldg(mb + 0) - 1.0f, ch0 = __ldg(mb + 1), cw0 = __ldg(mb + 2);
    float K0  = __ldg(mb + 3) - 0.5f * (cd0 * cdx + ch0 * chx + cw0 * cwx);
    float cd1 = __ldg(mb + 4), ch1 = __ldg(mb + 5) - 1.0f, cw1 = __ldg(mb + 6);
    float K1  = __ldg(mb + 7) - 0.5f * (cd1 * cdx + ch1 * chx + cw1 * cwx);
    float cd2 = __ldg(mb + 8), ch2 = __ldg(mb + 9), cw2 = __ldg(mb + 10) - 1.0f;
    float K2  = __ldg(mb + 11) - 0.5f * (cd2 * cdx + ch2 * chx + cw2 * cwx);

#pragma unroll
    for (int j = 0; j < ITERS; j++) {
        const unsigned local_v = j * VOX_PER_ITER + threadIdx.x * 4;
        const unsigned v = cta_base + local_v;

        // v % 4 == 0 and WW % 4 == 0: the 4 voxels share (d,h), w..w+3.
        unsigned w    = v % WW;
        unsigned rest = v / WW;
        unsigned h    = rest % HH;
        unsigned d    = (rest / HH) % DD;

        float fd = (float)d, fh = (float)h, fw = (float)w;

        float b0 = fmaf(cw0, fw, fmaf(ch0, fh, fmaf(cd0, fd, K0)));
        float b1 = fmaf(cw1, fw, fmaf(ch1, fh, fmaf(cd1, fd, K1)));
        float b2 = fmaf(cw2, fw, fmaf(ch2, fh, fmaf(cd2, fd, K2)));

        float4 o0 = make_float4(b0, b1, b2, b0 + cw0);
        float4 o1 = make_float4(b1 + cw1,
                                b2 + cw2,
                                fmaf(2.0f, cw0, b0),
                                fmaf(2.0f, cw1, b1));
        float4 o2 = make_float4(fmaf(2.0f, cw2, b2),
                                fmaf(3.0f, cw0, b0),
                                fmaf(3.0f, cw1, b1),
                                fmaf(3.0f, cw2, b2));

        // SMEM mirrors the global layout. Lane stride 48 B: conflict-free.
        float4* s = (float4*)(smem + (size_t)local_v * 3);
        s[0] = o0;
        s[1] = o1;
        s[2] = o2;

        // Chunk complete -> drain it while the next chunk computes.
        __syncthreads();
        if (threadIdx.x == 0) {
            asm volatile("fence.proxy.async.shared::cta;" ::: "memory");
            uint32_t saddr = (uint32_t)__cvta_generic_to_shared(
                smem + (size_t)j * CHUNK_FLOATS);
            float* gdst = out + (size_t)(cta_base + j * VOX_PER_ITER) * 3;
            uint32_t nbytes = CHUNK_BYTES;
            asm volatile(
                "cp.async.bulk.global.shared::cta.bulk_group [%0], [%1], %2;"
                :: "l"(gdst), "r"(saddr), "r"(nbytes)
                : "memory");
            asm volatile("cp.async.bulk.commit_group;" ::: "memory");
        }
    }

    // All committed bulk stores must finish reading smem before exit.
    if (threadIdx.x == 0) {
        asm volatile("cp.async.bulk.wait_group.read 0;" ::: "memory");
    }
    __syncthreads();
}

extern "C" void kernel_launch(void* const* d_in, const int* in_sizes, int n_in,
                              void* d_out, int out_size) {
    (void)in_sizes; (void)n_in; (void)out_size;
    const float* matrix = (const float*)d_in[0];
    float* out = (float*)d_out;

    affine_shift_kernel<<<GRID, THREADS>>>(matrix, out);
}

// round 5
// speedup vs baseline: 1.8232x; 1.0207x over previous
#include <cuda_runtime.h>
#include <cstdint>

// AffineToDenseShift: out[b,d,h,w,i] = K_i + cd_i*d + ch_i*h + cw_i*w
// (coefficients folded from A, t, and the centered mesh).
//
// R3 (TMA 48KB, occ 46%) and R4 (TMA 24KB chunked, occ 93%) both land at
// 47.5us kernel / DRAM 70% -> hard DRAM write-path ceiling (~6.95 TB/s
// effective = ~87% of spec). R5: add L2::evict_first cache hint to the bulk
// stores (zero-reuse output) to probe the last bit of DRAM headroom.

#define BB 4
#define DD 160
#define HH 192
#define WW 224
#define TOTAL_VOX (BB * DD * HH * WW)        // 27,525,120

#define THREADS 256
#define ITERS 2
#define VOX_PER_ITER (THREADS * 4)           // 1024 voxels per chunk
#define CTA_VOX (VOX_PER_ITER * ITERS)       // 2048 voxels per CTA
#define CHUNK_FLOATS (VOX_PER_ITER * 3)      // 3072 floats
#define CHUNK_BYTES (CHUNK_FLOATS * 4)       // 12288 B
#define CTA_FLOATS (CTA_VOX * 3)             // 6144 floats = 24 KB
#define GRID (TOTAL_VOX / CTA_VOX)           // 13440 CTAs (exact; 3360/batch)

__global__ void __launch_bounds__(THREADS)
affine_shift_kernel(const float* __restrict__ m, float* __restrict__ out) {
    __shared__ __align__(128) float smem[CTA_FLOATS];

    const unsigned cta_base = blockIdx.x * CTA_VOX;
    const unsigned b = cta_base / (DD * HH * WW);  // CTA never crosses a batch

    // Fold coefficients from matrix[b] (12 floats, L1-broadcast).
    const float* mb = m + b * 12;
    const float cdx = DD - 1, chx = HH - 1, cwx = WW - 1;

    float cd0 = __ldg(mb + 0) - 1.0f, ch0 = __ldg(mb + 1), cw0 = __ldg(mb + 2);
    float K0  = __ldg(mb + 3) - 0.5f * (cd0 * cdx + ch0 * chx + cw0 * cwx);
    float cd1 = __ldg(mb + 4), ch1 = __ldg(mb + 5) - 1.0f, cw1 = __ldg(mb + 6);
    float K1  = __ldg(mb + 7) - 0.5f * (cd1 * cdx + ch1 * chx + cw1 * cwx);
    float cd2 = __ldg(mb + 8), ch2 = __ldg(mb + 9), cw2 = __ldg(mb + 10) - 1.0f;
    float K2  = __ldg(mb + 11) - 0.5f * (cd2 * cdx + ch2 * chx + cw2 * cwx);

    // Streaming-write access policy: written lines are first to evict from L2.
    uint64_t policy;
    asm volatile("createpolicy.fractional.L2::evict_first.b64 %0, 1.0;"
                 : "=l"(policy));

#pragma unroll
    for (int j = 0; j < ITERS; j++) {
        const unsigned local_v = j * VOX_PER_ITER + threadIdx.x * 4;
        const unsigned v = cta_base + local_v;

        // v % 4 == 0 and WW % 4 == 0: the 4 voxels share (d,h), w..w+3.
        unsigned w    = v % WW;
        unsigned rest = v / WW;
        unsigned h    = rest % HH;
        unsigned d    = (rest / HH) % DD;

        float fd = (float)d, fh = (float)h, fw = (float)w;

        float b0 = fmaf(cw0, fw, fmaf(ch0, fh, fmaf(cd0, fd, K0)));
        float b1 = fmaf(cw1, fw, fmaf(ch1, fh, fmaf(cd1, fd, K1)));
        float b2 = fmaf(cw2, fw, fmaf(ch2, fh, fmaf(cd2, fd, K2)));

        float4 o0 = make_float4(b0, b1, b2, b0 + cw0);
        float4 o1 = make_float4(b1 + cw1,
                                b2 + cw2,
                                fmaf(2.0f, cw0, b0),
                                fmaf(2.0f, cw1, b1));
        float4 o2 = make_float4(fmaf(2.0f, cw2, b2),
                                fmaf(3.0f, cw0, b0),
                                fmaf(3.0f, cw1, b1),
                                fmaf(3.0f, cw2, b2));

        // SMEM mirrors the global layout. Lane stride 48 B: conflict-free.
        float4* s = (float4*)(smem + (size_t)local_v * 3);
        s[0] = o0;
        s[1] = o1;
        s[2] = o2;

        // Chunk complete -> drain it while the next chunk computes.
        __syncthreads();
        if (threadIdx.x == 0) {
            asm volatile("fence.proxy.async.shared::cta;" ::: "memory");
            uint32_t saddr = (uint32_t)__cvta_generic_to_shared(
                smem + (size_t)j * CHUNK_FLOATS);
            float* gdst = out + (size_t)(cta_base + j * VOX_PER_ITER) * 3;
            uint32_t nbytes = CHUNK_BYTES;
            asm volatile(
                "cp.async.bulk.global.shared::cta.bulk_group.L2::cache_hint"
                " [%0], [%1], %2, %3;"
                :: "l"(gdst), "r"(saddr), "r"(nbytes), "l"(policy)
                : "memory");
            asm volatile("cp.async.bulk.commit_group;" ::: "memory");
        }
    }

    // All committed bulk stores must finish reading smem before exit.
    if (threadIdx.x == 0) {
        asm volatile("cp.async.bulk.wait_group.read 0;" ::: "memory");
    }
    __syncthreads();
}

extern "C" void kernel_launch(void* const* d_in, const int* in_sizes, int n_in,
                              void* d_out, int out_size) {
    (void)in_sizes; (void)n_in; (void)out_size;
    const float* matrix = (const float*)d_in[0];
    float* out = (float*)d_out;

    affine_shift_kernel<<<GRID, THREADS>>>(matrix, out);
}